// round 10
// baseline (speedup 1.0000x reference)
#include <cuda_runtime.h>
#include <cuda_fp16.h>
#include <cstdint>

// Problem shape (fixed): x[B=4,S=4096,H=1024], conv_w[L=20,H,H], norm_w[H]
#define H_DIM   1024
#define L_DIM   20
#define M_TOTAL 16384
#define K_DIM   1024
#define N_DIM   1024
#define EPS     1e-6f

// ---- GEMM config ----
#define BM 128
#define BN 128
#define BKH 64                       // K-tile in halfs (128 B/row)
#define KTILES (K_DIM / BKH)         // 16
#define STAGES 3
#define A_STAGE_BYTES (BM * 128)     // 16384
#define B_STAGE_BYTES (BN * 128)     // 16384
#define STAGE_BYTES (A_STAGE_BYTES + B_STAGE_BYTES)   // 32768
#define SMEM_BYTES (STAGES * STAGE_BYTES)             // 98304 -> 2 CTAs/SM
#define NTHREADS 256
#define M_BLOCKS (M_TOTAL / BM)      // 128
#define N_BLOCKS (N_DIM / BN)        // 8

// fp16 scratch (device globals — allocation-free)
__device__ __half g_Wh[N_DIM * K_DIM];            // 2 MB
__device__ __half g_Xh[(size_t)M_TOTAL * K_DIM];  // 32 MB
__device__ __half g_Yh[(size_t)M_TOTAL * N_DIM];  // 32 MB (GEMM out, pre-norm)
__device__ int    g_cnt[M_BLOCKS];                // completion counters

#define PREP_W_BLOCKS ((H_DIM * H_DIM) / (256 * 8))                    // 512
#define PREP_X_BLOCKS ((int)(((size_t)M_TOTAL * K_DIM) / (256 * 8)))   // 8192

// ---------------------------------------------------------------------------
// Kernel 1 (fused prep): blocks [0,512) average conv_w -> g_Wh;
// blocks [512, 512+8192) convert x -> g_Xh. Block 0 also re-arms g_cnt.
// ---------------------------------------------------------------------------
__global__ void prep_kernel(const float* __restrict__ x,
                            const float* __restrict__ conv_w) {
    if (blockIdx.x == 0 && threadIdx.x < M_BLOCKS) g_cnt[threadIdx.x] = 0;
    if (blockIdx.x < PREP_W_BLOCKS) {
        int idx = (blockIdx.x * blockDim.x + threadIdx.x) * 8;
        const float inv = 1.0f / (float)L_DIM;
        float4 a0 = make_float4(0.f, 0.f, 0.f, 0.f);
        float4 a1 = make_float4(0.f, 0.f, 0.f, 0.f);
#pragma unroll
        for (int l = 0; l < L_DIM; l++) {
            const float* p = conv_w + (size_t)l * H_DIM * H_DIM + idx;
            float4 v0 = *(const float4*)(p);
            float4 v1 = *(const float4*)(p + 4);
            a0.x += v0.x; a0.y += v0.y; a0.z += v0.z; a0.w += v0.w;
            a1.x += v1.x; a1.y += v1.y; a1.z += v1.z; a1.w += v1.w;
        }
        __half2 h0 = __floats2half2_rn(a0.x * inv, a0.y * inv);
        __half2 h1 = __floats2half2_rn(a0.z * inv, a0.w * inv);
        __half2 h2 = __floats2half2_rn(a1.x * inv, a1.y * inv);
        __half2 h3 = __floats2half2_rn(a1.z * inv, a1.w * inv);
        *(uint4*)(g_Wh + idx) = make_uint4(*(uint32_t*)&h0, *(uint32_t*)&h1,
                                           *(uint32_t*)&h2, *(uint32_t*)&h3);
    } else {
        size_t idx = ((size_t)(blockIdx.x - PREP_W_BLOCKS) * blockDim.x + threadIdx.x) * 8;
        float4 v0 = *(const float4*)(x + idx);
        float4 v1 = *(const float4*)(x + idx + 4);
        __half2 h0 = __floats2half2_rn(v0.x, v0.y);
        __half2 h1 = __floats2half2_rn(v0.z, v0.w);
        __half2 h2 = __floats2half2_rn(v1.x, v1.y);
        __half2 h3 = __floats2half2_rn(v1.z, v1.w);
        *(uint4*)(g_Xh + idx) = make_uint4(*(uint32_t*)&h0, *(uint32_t*)&h1,
                                           *(uint32_t*)&h2, *(uint32_t*)&h3);
    }
}

// ---------------------------------------------------------------------------
// Kernel 2: y = x @ W^T (fp16 mma.sync, fp32 accum) -> g_Yh, then the LAST
// CTA of each M-block RMS-normalizes its 128 rows (L2-hot) -> out (fp32).
// ---------------------------------------------------------------------------
__device__ __forceinline__ uint32_t smem_u32(const void* p) {
    uint32_t a;
    asm("{ .reg .u64 t; cvta.to.shared.u64 t, %1; cvt.u32.u64 %0, t; }" : "=r"(a) : "l"(p));
    return a;
}
__device__ __forceinline__ void ldsm_x4(uint32_t& r0, uint32_t& r1, uint32_t& r2, uint32_t& r3,
                                        uint32_t addr) {
    asm volatile("ldmatrix.sync.aligned.m8n8.x4.shared.b16 {%0,%1,%2,%3}, [%4];"
                 : "=r"(r0), "=r"(r1), "=r"(r2), "=r"(r3) : "r"(addr));
}

__global__ __launch_bounds__(NTHREADS, 2)
void gemm_f16_kernel(float* __restrict__ out, const float* __restrict__ nw) {
    extern __shared__ char smem[];
    const uint32_t sbase = smem_u32(smem);
    __shared__ int s_last;

    const int tid  = threadIdx.x;
    const int warp = tid >> 5;
    const int lane = tid & 31;
    const int wm   = warp >> 2;          // 0..1 -> m offset wm*64
    const int wn   = warp & 3;           // 0..3 -> n offset wn*32
    const int g    = lane >> 2;
    const int tg   = lane & 3;
    const int quad = lane >> 3;
    const int lrow = lane & 7;

    const int bm = blockIdx.y * BM;
    const int bn = blockIdx.x * BN;

    const int arow = tid >> 3, ac = tid & 7;
    const uint32_t soff = (uint32_t)(((arow << 3) + (ac ^ (arow & 7))) * 16);

    float acc[4][4][4];
#pragma unroll
    for (int mi = 0; mi < 4; mi++)
#pragma unroll
        for (int ni = 0; ni < 4; ni++)
#pragma unroll
            for (int c = 0; c < 4; c++) acc[mi][ni][c] = 0.f;

    auto load_A = [&](int s, int t) {
        const uint32_t ab = sbase + s * STAGE_BYTES;
        const int k0 = t * BKH;
#pragma unroll
        for (int i = 0; i < 4; i++) {
            const uint32_t dst = ab + soff + (uint32_t)(i * 32 * 128);
            const __half* src = g_Xh + (size_t)(bm + arow + i * 32) * K_DIM + k0 + ac * 8;
            asm volatile("cp.async.cg.shared.global [%0], [%1], 16;"
                         :: "r"(dst), "l"(src) : "memory");
        }
    };
    auto load_B = [&](int s, int t) {
        const uint32_t bb = sbase + s * STAGE_BYTES + A_STAGE_BYTES;
        const int k0 = t * BKH;
#pragma unroll
        for (int i = 0; i < 4; i++) {
            const uint32_t dst = bb + soff + (uint32_t)(i * 32 * 128);
            const __half* src = g_Wh + (size_t)(bn + arow + i * 32) * K_DIM + k0 + ac * 8;
            asm volatile("cp.async.cg.shared.global [%0], [%1], 16;"
                         :: "r"(dst), "l"(src) : "memory");
        }
    };

    auto compute_tile = [&](int s, int sl, int tl, bool do_load) {
        const uint32_t ab = sbase + s * STAGE_BYTES;
        const uint32_t bb = ab + A_STAGE_BYTES;
#pragma unroll
        for (int kk = 0; kk < 4; kk++) {
            if (do_load) {
                if (kk == 0) load_A(sl, tl);
                else if (kk == 1) load_B(sl, tl);
            }
            uint32_t a[4][4];
#pragma unroll
            for (int mi = 0; mi < 4; mi++) {
                const int r = wm * 64 + mi * 16 + (quad & 1) * 8 + lrow;
                const int c = 2 * kk + (quad >> 1);
                ldsm_x4(a[mi][0], a[mi][1], a[mi][2], a[mi][3],
                        ab + ((r << 3) + (c ^ (r & 7))) * 16);
            }
#pragma unroll
            for (int np = 0; np < 2; np++) {
                const int n = wn * 32 + np * 16 + (quad >> 1) * 8 + lrow;
                const int c = 2 * kk + (quad & 1);
                uint32_t b0, b1, b2, b3;
                ldsm_x4(b0, b1, b2, b3, bb + ((n << 3) + (c ^ (n & 7))) * 16);
#pragma unroll
                for (int mi = 0; mi < 4; mi++) {
                    asm volatile(
                        "mma.sync.aligned.m16n8k16.row.col.f32.f16.f16.f32 "
                        "{%0,%1,%2,%3}, {%4,%5,%6,%7}, {%8,%9}, {%0,%1,%2,%3};"
                        : "+f"(acc[mi][2*np][0]), "+f"(acc[mi][2*np][1]),
                          "+f"(acc[mi][2*np][2]), "+f"(acc[mi][2*np][3])
                        : "r"(a[mi][0]), "r"(a[mi][1]), "r"(a[mi][2]), "r"(a[mi][3]),
                          "r"(b0), "r"(b1));
                    asm volatile(
                        "mma.sync.aligned.m16n8k16.row.col.f32.f16.f16.f32 "
                        "{%0,%1,%2,%3}, {%4,%5,%6,%7}, {%8,%9}, {%0,%1,%2,%3};"
                        : "+f"(acc[mi][2*np+1][0]), "+f"(acc[mi][2*np+1][1]),
                          "+f"(acc[mi][2*np+1][2]), "+f"(acc[mi][2*np+1][3])
                        : "r"(a[mi][0]), "r"(a[mi][1]), "r"(a[mi][2]), "r"(a[mi][3]),
                          "r"(b2), "r"(b3));
                }
            }
        }
    };

    // ---- prologue ----
#pragma unroll
    for (int s = 0; s < STAGES - 1; s++) {
        load_A(s, s); load_B(s, s);
        asm volatile("cp.async.commit_group;" ::: "memory");
    }

    // ---- mainloop ----
    int cs = 0, ls = STAGES - 1;
#pragma unroll 1
    for (int t = 0; t < KTILES; t++) {
        asm volatile("cp.async.wait_group %0;" :: "n"(STAGES - 2) : "memory");
        __syncthreads();
        compute_tile(cs, ls, t + STAGES - 1, t + STAGES - 1 < KTILES);
        asm volatile("cp.async.commit_group;" ::: "memory");
        if (++cs == STAGES) cs = 0;
        if (++ls == STAGES) ls = 0;
    }

    // ---- epilogue: fp16 stores to g_Yh ----
#pragma unroll
    for (int mi = 0; mi < 4; mi++) {
#pragma unroll
        for (int ni = 0; ni < 4; ni++) {
            const int row = bm + wm * 64 + mi * 16 + g;
            const int col = bn + wn * 32 + ni * 8 + tg * 2;
            __half2 h01 = __floats2half2_rn(acc[mi][ni][0], acc[mi][ni][1]);
            __half2 h23 = __floats2half2_rn(acc[mi][ni][2], acc[mi][ni][3]);
            *(uint32_t*)(g_Yh + (size_t)row       * N_DIM + col) = *(uint32_t*)&h01;
            *(uint32_t*)(g_Yh + (size_t)(row + 8) * N_DIM + col) = *(uint32_t*)&h23;
        }
    }

    // ---- completion count: last CTA of this M-block does the RMSNorm ----
    __threadfence();
    __syncthreads();
    if (tid == 0)
        s_last = (atomicAdd(&g_cnt[blockIdx.y], 1) == N_BLOCKS - 1);
    __syncthreads();
    if (!s_last) return;
    __threadfence();

    // normalize rows [bm, bm+128): warp-per-row, 16 rounds of 8 rows.
#pragma unroll 1
    for (int rr = 0; rr < BM / 8; rr++) {
        const size_t row = (size_t)bm + rr * 8 + warp;
        const uint4* p = (const uint4*)(g_Yh + row * N_DIM);   // L2-hot
        float* o = out + row * N_DIM;

        float2 f[4][4];
        float ss = 0.f;
#pragma unroll
        for (int i = 0; i < 4; i++) {
            uint4 h = p[lane + i * 32];
            f[i][0] = __half22float2(*(__half2*)&h.x);
            f[i][1] = __half22float2(*(__half2*)&h.y);
            f[i][2] = __half22float2(*(__half2*)&h.z);
            f[i][3] = __half22float2(*(__half2*)&h.w);
#pragma unroll
            for (int j = 0; j < 4; j++)
                ss += f[i][j].x * f[i][j].x + f[i][j].y * f[i][j].y;
        }
#pragma unroll
        for (int of = 16; of; of >>= 1) ss += __shfl_xor_sync(0xFFFFFFFFu, ss, of);

        const float scale = rsqrtf(ss * (1.0f / H_DIM) + EPS);
#pragma unroll
        for (int i = 0; i < 4; i++) {
            const int base = lane * 8 + i * 256;
            float4 w0 = *(const float4*)(nw + base);
            float4 w1 = *(const float4*)(nw + base + 4);
            float4 o0, o1;
            o0.x = f[i][0].x * scale * w0.x;
            o0.y = f[i][0].y * scale * w0.y;
            o0.z = f[i][1].x * scale * w0.z;
            o0.w = f[i][1].y * scale * w0.w;
            o1.x = f[i][2].x * scale * w1.x;
            o1.y = f[i][2].y * scale * w1.y;
            o1.z = f[i][3].x * scale * w1.z;
            o1.w = f[i][3].y * scale * w1.w;
            *(float4*)(o + base)     = o0;
            *(float4*)(o + base + 4) = o1;
        }
    }
}

// ---------------------------------------------------------------------------
extern "C" void kernel_launch(void* const* d_in, const int* in_sizes, int n_in,
                              void* d_out, int out_size) {
    const float* x      = (const float*)d_in[0];
    const float* conv_w = (const float*)d_in[1];
    const float* norm_w = (const float*)d_in[2];
    float* out = (float*)d_out;

    cudaFuncSetAttribute(gemm_f16_kernel,
                         cudaFuncAttributeMaxDynamicSharedMemorySize, SMEM_BYTES);

    prep_kernel<<<PREP_W_BLOCKS + PREP_X_BLOCKS, 256>>>(x, conv_w);

    dim3 grid(N_BLOCKS, M_BLOCKS);   // 8 x 128 = 1024 CTAs, 2/SM
    gemm_f16_kernel<<<grid, NTHREADS, SMEM_BYTES>>>(out, norm_w);
}

// round 11
// speedup vs baseline: 1.1267x; 1.1267x over previous
#include <cuda_runtime.h>
#include <cuda_fp16.h>
#include <cstdint>

// Problem shape (fixed): x[B=4,S=4096,H=1024], conv_w[L=20,H,H], norm_w[H]
#define H_DIM   1024
#define L_DIM   20
#define M_TOTAL 16384
#define K_DIM   1024
#define N_DIM   1024
#define EPS     1e-6f

// ---- GEMM config: 64x128 CTA tile, 3 stages, 3 CTAs/SM ----
#define BM 64
#define BN 128
#define BKH 64                       // K-tile in halfs (128 B/row)
#define KTILES (K_DIM / BKH)         // 16
#define STAGES 3
#define A_STAGE_BYTES (BM * 128)     // 8192
#define B_STAGE_BYTES (BN * 128)     // 16384
#define STAGE_BYTES (A_STAGE_BYTES + B_STAGE_BYTES)   // 24576
#define SMEM_BYTES (STAGES * STAGE_BYTES)             // 73728 -> 3 CTAs/SM
#define NTHREADS 256

// fp16 scratch (device globals — allocation-free)
__device__ __half g_Wh[N_DIM * K_DIM];            // 2 MB
__device__ __half g_Xh[(size_t)M_TOTAL * K_DIM];  // 32 MB
__device__ __half g_Yh[(size_t)M_TOTAL * N_DIM];  // 32 MB (GEMM out, pre-norm)

#define PREP_W_BLOCKS ((H_DIM * H_DIM) / (256 * 8))                    // 512
#define PREP_X_BLOCKS ((int)(((size_t)M_TOTAL * K_DIM) / (256 * 8)))   // 8192

// ---------------------------------------------------------------------------
// Kernel 1 (fused prep): blocks [0,512) average conv_w -> g_Wh;
// blocks [512, 512+8192) convert x -> g_Xh.
// ---------------------------------------------------------------------------
__global__ void prep_kernel(const float* __restrict__ x,
                            const float* __restrict__ conv_w) {
    if (blockIdx.x < PREP_W_BLOCKS) {
        int idx = (blockIdx.x * blockDim.x + threadIdx.x) * 8;
        const float inv = 1.0f / (float)L_DIM;
        float4 a0 = make_float4(0.f, 0.f, 0.f, 0.f);
        float4 a1 = make_float4(0.f, 0.f, 0.f, 0.f);
#pragma unroll
        for (int l = 0; l < L_DIM; l++) {
            const float* p = conv_w + (size_t)l * H_DIM * H_DIM + idx;
            float4 v0 = *(const float4*)(p);
            float4 v1 = *(const float4*)(p + 4);
            a0.x += v0.x; a0.y += v0.y; a0.z += v0.z; a0.w += v0.w;
            a1.x += v1.x; a1.y += v1.y; a1.z += v1.z; a1.w += v1.w;
        }
        __half2 h0 = __floats2half2_rn(a0.x * inv, a0.y * inv);
        __half2 h1 = __floats2half2_rn(a0.z * inv, a0.w * inv);
        __half2 h2 = __floats2half2_rn(a1.x * inv, a1.y * inv);
        __half2 h3 = __floats2half2_rn(a1.z * inv, a1.w * inv);
        *(uint4*)(g_Wh + idx) = make_uint4(*(uint32_t*)&h0, *(uint32_t*)&h1,
                                           *(uint32_t*)&h2, *(uint32_t*)&h3);
    } else {
        size_t idx = ((size_t)(blockIdx.x - PREP_W_BLOCKS) * blockDim.x + threadIdx.x) * 8;
        float4 v0 = *(const float4*)(x + idx);
        float4 v1 = *(const float4*)(x + idx + 4);
        __half2 h0 = __floats2half2_rn(v0.x, v0.y);
        __half2 h1 = __floats2half2_rn(v0.z, v0.w);
        __half2 h2 = __floats2half2_rn(v1.x, v1.y);
        __half2 h3 = __floats2half2_rn(v1.z, v1.w);
        *(uint4*)(g_Xh + idx) = make_uint4(*(uint32_t*)&h0, *(uint32_t*)&h1,
                                           *(uint32_t*)&h2, *(uint32_t*)&h3);
    }
}

// ---------------------------------------------------------------------------
// Kernel 2: y = x @ W^T  (fp16 mma.sync m16n8k16, fp32 accum) -> g_Yh (fp16)
// CTA 64x128xK64, 8 warps = 2(m) x 4(n), warp tile 32x32.
// 3-stage cp.async pipeline, 3 CTAs/SM (24 warps). Loads interleaved in kk.
// ---------------------------------------------------------------------------
__device__ __forceinline__ uint32_t smem_u32(const void* p) {
    uint32_t a;
    asm("{ .reg .u64 t; cvta.to.shared.u64 t, %1; cvt.u32.u64 %0, t; }" : "=r"(a) : "l"(p));
    return a;
}
__device__ __forceinline__ void ldsm_x4(uint32_t& r0, uint32_t& r1, uint32_t& r2, uint32_t& r3,
                                        uint32_t addr) {
    asm volatile("ldmatrix.sync.aligned.m8n8.x4.shared.b16 {%0,%1,%2,%3}, [%4];"
                 : "=r"(r0), "=r"(r1), "=r"(r2), "=r"(r3) : "r"(addr));
}

__global__ __launch_bounds__(NTHREADS, 3)
void gemm_f16_kernel() {
    extern __shared__ char smem[];
    const uint32_t sbase = smem_u32(smem);

    const int tid  = threadIdx.x;
    const int warp = tid >> 5;
    const int lane = tid & 31;
    const int wm   = warp >> 2;          // 0..1 -> m offset wm*32
    const int wn   = warp & 3;           // 0..3 -> n offset wn*32
    const int g    = lane >> 2;
    const int tg   = lane & 3;
    const int quad = lane >> 3;
    const int lrow = lane & 7;

    const int bm = blockIdx.y * BM;
    const int bn = blockIdx.x * BN;

    const int arow = tid >> 3, ac = tid & 7;    // rows 0..31 (+i*32), col chunk
    const uint32_t soff = (uint32_t)(((arow << 3) + (ac ^ (arow & 7))) * 16);

    float acc[2][4][4];
#pragma unroll
    for (int mi = 0; mi < 2; mi++)
#pragma unroll
        for (int ni = 0; ni < 4; ni++)
#pragma unroll
            for (int c = 0; c < 4; c++) acc[mi][ni][c] = 0.f;

    auto load_A = [&](int s, int t) {           // 64 rows -> 2 chunks/thread
        const uint32_t ab = sbase + s * STAGE_BYTES;
        const int k0 = t * BKH;
#pragma unroll
        for (int i = 0; i < 2; i++) {
            const uint32_t dst = ab + soff + (uint32_t)(i * 32 * 128);
            const __half* src = g_Xh + (size_t)(bm + arow + i * 32) * K_DIM + k0 + ac * 8;
            asm volatile("cp.async.cg.shared.global [%0], [%1], 16;"
                         :: "r"(dst), "l"(src) : "memory");
        }
    };
    auto load_B = [&](int s, int t) {           // 128 rows -> 4 chunks/thread
        const uint32_t bb = sbase + s * STAGE_BYTES + A_STAGE_BYTES;
        const int k0 = t * BKH;
#pragma unroll
        for (int i = 0; i < 4; i++) {
            const uint32_t dst = bb + soff + (uint32_t)(i * 32 * 128);
            const __half* src = g_Wh + (size_t)(bn + arow + i * 32) * K_DIM + k0 + ac * 8;
            asm volatile("cp.async.cg.shared.global [%0], [%1], 16;"
                         :: "r"(dst), "l"(src) : "memory");
        }
    };

    auto compute_tile = [&](int s, int sl, int tl, bool do_load) {
        const uint32_t ab = sbase + s * STAGE_BYTES;
        const uint32_t bb = ab + A_STAGE_BYTES;
#pragma unroll
        for (int kk = 0; kk < 4; kk++) {
            if (do_load) {
                if (kk == 0) load_A(sl, tl);
                else if (kk == 1) load_B(sl, tl);
            }
            uint32_t a[2][4];
#pragma unroll
            for (int mi = 0; mi < 2; mi++) {
                const int r = wm * 32 + mi * 16 + (quad & 1) * 8 + lrow;
                const int c = 2 * kk + (quad >> 1);
                ldsm_x4(a[mi][0], a[mi][1], a[mi][2], a[mi][3],
                        ab + ((r << 3) + (c ^ (r & 7))) * 16);
            }
#pragma unroll
            for (int np = 0; np < 2; np++) {
                const int n = wn * 32 + np * 16 + (quad >> 1) * 8 + lrow;
                const int c = 2 * kk + (quad & 1);
                uint32_t b0, b1, b2, b3;
                ldsm_x4(b0, b1, b2, b3, bb + ((n << 3) + (c ^ (n & 7))) * 16);
#pragma unroll
                for (int mi = 0; mi < 2; mi++) {
                    asm volatile(
                        "mma.sync.aligned.m16n8k16.row.col.f32.f16.f16.f32 "
                        "{%0,%1,%2,%3}, {%4,%5,%6,%7}, {%8,%9}, {%0,%1,%2,%3};"
                        : "+f"(acc[mi][2*np][0]), "+f"(acc[mi][2*np][1]),
                          "+f"(acc[mi][2*np][2]), "+f"(acc[mi][2*np][3])
                        : "r"(a[mi][0]), "r"(a[mi][1]), "r"(a[mi][2]), "r"(a[mi][3]),
                          "r"(b0), "r"(b1));
                    asm volatile(
                        "mma.sync.aligned.m16n8k16.row.col.f32.f16.f16.f32 "
                        "{%0,%1,%2,%3}, {%4,%5,%6,%7}, {%8,%9}, {%0,%1,%2,%3};"
                        : "+f"(acc[mi][2*np+1][0]), "+f"(acc[mi][2*np+1][1]),
                          "+f"(acc[mi][2*np+1][2]), "+f"(acc[mi][2*np+1][3])
                        : "r"(a[mi][0]), "r"(a[mi][1]), "r"(a[mi][2]), "r"(a[mi][3]),
                          "r"(b2), "r"(b3));
                }
            }
        }
    };

    // ---- prologue: stages 0,1 ----
#pragma unroll
    for (int s = 0; s < STAGES - 1; s++) {
        load_A(s, s); load_B(s, s);
        asm volatile("cp.async.commit_group;" ::: "memory");
    }

    // ---- mainloop ----
    int cs = 0, ls = STAGES - 1;
#pragma unroll 1
    for (int t = 0; t < KTILES; t++) {
        asm volatile("cp.async.wait_group %0;" :: "n"(STAGES - 2) : "memory");
        __syncthreads();
        compute_tile(cs, ls, t + STAGES - 1, t + STAGES - 1 < KTILES);
        asm volatile("cp.async.commit_group;" ::: "memory");
        if (++cs == STAGES) cs = 0;
        if (++ls == STAGES) ls = 0;
    }

    // ---- epilogue: fp16 stores to g_Yh ----
#pragma unroll
    for (int mi = 0; mi < 2; mi++) {
#pragma unroll
        for (int ni = 0; ni < 4; ni++) {
            const int row = bm + wm * 32 + mi * 16 + g;
            const int col = bn + wn * 32 + ni * 8 + tg * 2;
            __half2 h01 = __floats2half2_rn(acc[mi][ni][0], acc[mi][ni][1]);
            __half2 h23 = __floats2half2_rn(acc[mi][ni][2], acc[mi][ni][3]);
            *(uint32_t*)(g_Yh + (size_t)row       * N_DIM + col) = *(uint32_t*)&h01;
            *(uint32_t*)(g_Yh + (size_t)(row + 8) * N_DIM + col) = *(uint32_t*)&h23;
        }
    }
}

// ---------------------------------------------------------------------------
// Kernel 3: RMSNorm g_Yh (fp16) -> out (fp32), warp-per-row.
// ---------------------------------------------------------------------------
__global__ __launch_bounds__(256)
void rmsnorm_kernel(float* __restrict__ out, const float* __restrict__ nw) {
    const int warp = threadIdx.x >> 5;
    const int lane = threadIdx.x & 31;
    const size_t row = (size_t)blockIdx.x * 8 + warp;
    const uint4* p = (const uint4*)(g_Yh + row * H_DIM);
    float* o = out + row * H_DIM;

    float2 f[4][4];
    float ss = 0.f;
#pragma unroll
    for (int i = 0; i < 4; i++) {
        uint4 h = p[lane + i * 32];
        f[i][0] = __half22float2(*(__half2*)&h.x);
        f[i][1] = __half22float2(*(__half2*)&h.y);
        f[i][2] = __half22float2(*(__half2*)&h.z);
        f[i][3] = __half22float2(*(__half2*)&h.w);
#pragma unroll
        for (int j = 0; j < 4; j++)
            ss += f[i][j].x * f[i][j].x + f[i][j].y * f[i][j].y;
    }
#pragma unroll
    for (int of = 16; of; of >>= 1) ss += __shfl_xor_sync(0xFFFFFFFFu, ss, of);

    const float scale = rsqrtf(ss * (1.0f / H_DIM) + EPS);
#pragma unroll
    for (int i = 0; i < 4; i++) {
        const int base = lane * 8 + i * 256;
        float4 w0 = *(const float4*)(nw + base);
        float4 w1 = *(const float4*)(nw + base + 4);
        float4 o0, o1;
        o0.x = f[i][0].x * scale * w0.x;
        o0.y = f[i][0].y * scale * w0.y;
        o0.z = f[i][1].x * scale * w0.z;
        o0.w = f[i][1].y * scale * w0.w;
        o1.x = f[i][2].x * scale * w1.x;
        o1.y = f[i][2].y * scale * w1.y;
        o1.z = f[i][3].x * scale * w1.z;
        o1.w = f[i][3].y * scale * w1.w;
        *(float4*)(o + base)     = o0;
        *(float4*)(o + base + 4) = o1;
    }
}

// ---------------------------------------------------------------------------
extern "C" void kernel_launch(void* const* d_in, const int* in_sizes, int n_in,
                              void* d_out, int out_size) {
    const float* x      = (const float*)d_in[0];
    const float* conv_w = (const float*)d_in[1];
    const float* norm_w = (const float*)d_in[2];
    float* out = (float*)d_out;

    cudaFuncSetAttribute(gemm_f16_kernel,
                         cudaFuncAttributeMaxDynamicSharedMemorySize, SMEM_BYTES);

    prep_kernel<<<PREP_W_BLOCKS + PREP_X_BLOCKS, 256>>>(x, conv_w);

    dim3 grid(N_DIM / BN, M_TOTAL / BM);   // 8 x 256 = 2048 CTAs, 3/SM
    gemm_f16_kernel<<<grid, NTHREADS, SMEM_BYTES>>>();

    rmsnorm_kernel<<<M_TOTAL / 8, 256>>>(out, norm_w);
}